// round 15
// baseline (speedup 1.0000x reference)
#include <cuda_runtime.h>
#include <cuda_fp16.h>
#include <math.h>
#include <stdint.h>

#define DD   1024
#define FF   2752
#define EE   8
#define NTOK 8192
#define NA   16384
#define NB13 (2*FF)   /* 5504 */
#define MT256 10      /* m-tile (256-row) capacity/expert: 2560 rows */
#define ECAP  2560

// ---------------- scratch (static device globals; no allocation) ----------
__device__ int   g_cursor[EE];
__device__ int   g_atok[EE * ECAP];
__device__ int   g_aslot[EE * ECAP];
__device__ float g_aw[EE * ECAP];

__device__ __half g_xf[(size_t)NTOK * DD];            // fp16 x
__device__ __half g_W13f[(size_t)EE * NB13 * DD];     // K-major [E][N][K]
__device__ __half g_W2f[(size_t)EE * DD * FF];        // K-major [E][N][K]
__device__ __half g_Hf[(size_t)EE * ECAP * FF];       // fp16 H (capacity layout)
__device__ float  g_OutK[2][(size_t)NTOK * DD];

// ---------------- helpers ---------------------------------------------------
__device__ __forceinline__ uint32_t smem_u32(const void* p) {
    uint32_t a;
    asm("{ .reg .u64 t; cvta.to.shared.u64 t, %1; cvt.u32.u64 %0, t; }"
        : "=r"(a) : "l"(p));
    return a;
}
#define CPA16(dst, src) \
    asm volatile("cp.async.cg.shared.global [%0], [%1], 16;\n" :: "r"(dst), "l"(src) : "memory")
#define CPA_COMMIT()  asm volatile("cp.async.commit_group;\n" ::: "memory")
#define CPA_WAIT1()   asm volatile("cp.async.wait_group 1;\n" ::: "memory")

#define HMMA(d, a0, a1, a2, a3, b0, b1)                                        \
    asm volatile(                                                              \
        "mma.sync.aligned.m16n8k16.row.col.f32.f16.f16.f32 "                   \
        "{%0,%1,%2,%3}, {%4,%5,%6,%7}, {%8,%9}, {%0,%1,%2,%3};\n"              \
        : "+f"((d)[0]), "+f"((d)[1]), "+f"((d)[2]), "+f"((d)[3])               \
        : "r"(a0), "r"(a1), "r"(a2), "r"(a3), "r"(b0), "r"(b1))

#define LDSM4(r0, r1, r2, r3, addr)                                            \
    asm volatile("ldmatrix.sync.aligned.m8n8.x4.shared.b16 {%0,%1,%2,%3}, [%4];" \
        : "=r"(r0), "=r"(r1), "=r"(r2), "=r"(r3) : "r"(addr))

// ---------------- small kernels -------------------------------------------
// transpose: src fp32 [E][KSRC][NSRC] -> dst fp16 K-major [E][NSRC][KSRC]
// W13SEL variant also zeroes the per-expert cursors (runs first in the chain).
template <int KSRC, int NSRC, int W13SEL>
__global__ void trans_f16_kernel(const float* __restrict__ src) {
    __shared__ float tile[64][33];
    const int e  = blockIdx.z;
    const int n0 = blockIdx.x * 32;
    const int k0 = blockIdx.y * 64;
    const int tx = threadIdx.x, ty = threadIdx.y;  // (32, 8)
    if (W13SEL && blockIdx.x == 0 && blockIdx.y == 0 && blockIdx.z == 0 &&
        ty == 0 && tx < EE) {
        g_cursor[tx] = 0;
    }
    const float* s = src + (size_t)e * KSRC * NSRC;
#pragma unroll
    for (int i = 0; i < 8; i++) {
        int k = ty + i * 8;
        tile[k][tx] = s[(size_t)(k0 + k) * NSRC + n0 + tx];
    }
    __syncthreads();
    __half* d = (W13SEL ? g_W13f : g_W2f) + (size_t)e * NSRC * KSRC;
#pragma unroll
    for (int i = 0; i < 4; i++) {
        int ny = ty + i * 8;
        __half2 p = __floats2half2_rn(tile[2 * tx][ny], tile[2 * tx + 1][ny]);
        *(__half2*)(d + (size_t)(n0 + ny) * KSRC + k0 + 2 * tx) = p;
    }
}

// router + fp16 conversion of x + direct assignment-list build (fused).
__global__ void router_kernel(const float* __restrict__ x,
                              const float* __restrict__ Wr) {
    int warp = (int)((blockIdx.x * blockDim.x + threadIdx.x) >> 5);
    int lane = threadIdx.x & 31;
    if (warp >= NTOK) return;
    const float* xr = x + (size_t)warp * DD;
    float acc[EE];
#pragma unroll
    for (int e = 0; e < EE; e++) acc[e] = 0.f;
    for (int d4 = lane; d4 < DD / 4; d4 += 32) {
        float4 v = ((const float4*)xr)[d4];
        __half2 p0 = __floats2half2_rn(v.x, v.y);
        __half2 p1 = __floats2half2_rn(v.z, v.w);
        *(uint2*)(g_xf + (size_t)warp * DD + d4 * 4) =
            make_uint2(*(uint32_t*)&p0, *(uint32_t*)&p1);
        const float* xv4 = (const float*)&v;
#pragma unroll
        for (int q = 0; q < 4; q++) {
            float xv = xv4[q];
            const float4* wp = (const float4*)(Wr + (size_t)(d4 * 4 + q) * EE);
            float4 w0 = wp[0], w1 = wp[1];
            acc[0] += xv * w0.x; acc[1] += xv * w0.y;
            acc[2] += xv * w0.z; acc[3] += xv * w0.w;
            acc[4] += xv * w1.x; acc[5] += xv * w1.y;
            acc[6] += xv * w1.z; acc[7] += xv * w1.w;
        }
    }
#pragma unroll
    for (int e = 0; e < EE; e++) {
#pragma unroll
        for (int o = 16; o; o >>= 1)
            acc[e] += __shfl_xor_sync(0xffffffffu, acc[e], o);
    }
    if (lane == 0) {
        int i0 = 0;
#pragma unroll
        for (int e = 1; e < EE; e++) if (acc[e] > acc[i0]) i0 = e;
        int i1 = (i0 == 0) ? 1 : 0;
#pragma unroll
        for (int e = 0; e < EE; e++)
            if (e != i0 && acc[e] > acc[i1]) i1 = e;
        float w0 = 1.f / (1.f + expf(acc[i1] - acc[i0]));
        float w1 = 1.f - w0;
        int p0 = atomicAdd(&g_cursor[i0], 1);
        int a0 = i0 * ECAP + p0;
        g_atok[a0] = warp; g_aslot[a0] = 0; g_aw[a0] = w0;
        int p1 = atomicAdd(&g_cursor[i1], 1);
        int a1 = i1 * ECAP + p1;
        g_atok[a1] = warp; g_aslot[a1] = 1; g_aw[a1] = w1;
    }
}

// ---------------- fp16 tensor-core grouped GEMM (fat-warp, L1-lean) --------
// CTA tile: M=256, 256 threads, 1 CTA/SM (256 regs/thread), K-chunk 32,
// 3-stage cp.async. 8 warps = 4(m:64) x 2(n:32-pair); warp tile 64m x 64n
// (acc 128 regs) -> L1 bytes/MAC cut 36% vs 128m CTA (the measured binder:
// L1=68.6%, tensor=37.8%).
//   G1: N = 64 gate + 64 up (fused SwiGLU -> fp16 H); grid m-fastest.
//   G2: N = 128 out cols (scaled scatter to OutK); grid nb-fastest.
// smem/stage: A[256 rows][80B] + B[128 rows][80B] = 30720B; 3 stages.
// rows = 32 fp16 of K (64B data + 16B pad). ldmatrix.m8n8.x4 fragments.

#define STAGE_B   30720u
#define SMEM_GEMM (3 * 30720)

template <bool G1>
__global__ void __launch_bounds__(256, 1)
hgemm_tc_kernel() {
    constexpr int KDIM = G1 ? DD : FF;
    constexpr int KT   = KDIM / 32;

    const int e     = blockIdx.z;
    const int cnt   = g_cursor[e];
    const int mtile = G1 ? blockIdx.x : blockIdx.y;   // G2: nb-fastest
    const int nb    = G1 ? blockIdx.y : blockIdx.x;
    const int mbase = mtile * 256;
    if (mbase >= cnt) return;
    const int off = e * ECAP;

    extern __shared__ __align__(16) uint32_t smw[];
    const uint32_t sb = smem_u32(smw);

    const int tid  = threadIdx.x;
    const int warp = tid >> 5, lane = tid & 31;
    const int grp  = lane >> 2, tig = lane & 3;
    const int mrow0 = (warp >> 1) * 64;
    const int ncol0 = (warp & 1) * 32;

    // ldmatrix per-lane offsets (bytes within a tile, 80B row stride):
    const uint32_t lmA = (uint32_t)(((lane & 7) + ((lane >> 3) & 1) * 8) * 80
                                    + (lane >> 4) * 16);
    const uint32_t lmB = (uint32_t)(((lane & 7) + (lane >> 4) * 8) * 80
                                    + ((lane >> 3) & 1) * 16);

    // ---- A fill: thread -> row tid (0..255), 4 x 16B (full 64B row) ----
    const __half* aP;
    {
        int rg = mbase + tid; if (rg >= cnt) rg = cnt - 1;
        if (G1) aP = g_xf + (size_t)g_atok[off + rg] * DD;
        else    aP = g_Hf + (size_t)(off + rg) * FF;
    }
    const uint32_t offA = (uint32_t)tid * 80u;
    // ---- B fill: thread -> row tid&127, half tid>>7; 2 x 16B ----
    const int br = tid & 127, bh = tid >> 7;
    const __half* bP;
    {
        if (G1) {
            int n = (br < 64) ? (nb * 64 + br) : (FF + nb * 64 + (br - 64));
            bP = g_W13f + ((size_t)e * NB13 + n) * DD + bh * 16;
        } else {
            int n = nb * 128 + br;
            bP = g_W2f + ((size_t)e * DD + n) * FF + bh * 16;
        }
    }
    const uint32_t offB = 20480u + (uint32_t)br * 80u + (uint32_t)bh * 32u;

#define FILL(st, kt) do {                                                      \
    uint32_t _a = sb + (uint32_t)(st) * STAGE_B + offA;                        \
    uint32_t _b = sb + (uint32_t)(st) * STAGE_B + offB;                        \
    const __half* _as = aP + (kt) * 32;                                        \
    const __half* _bs = bP + (kt) * 32;                                        \
    CPA16(_a,      _as);                                                       \
    CPA16(_a + 16, _as + 8);                                                   \
    CPA16(_a + 32, _as + 16);                                                  \
    CPA16(_a + 48, _as + 24);                                                  \
    CPA16(_b,      _bs);                                                       \
    CPA16(_b + 16, _bs + 8);                                                   \
} while (0)

    float acc[2][4][4][4];   // [set][mf][nf][frag]
#pragma unroll
    for (int s = 0; s < 2; s++)
#pragma unroll
        for (int a = 0; a < 4; a++)
#pragma unroll
            for (int b = 0; b < 4; b++)
#pragma unroll
                for (int c = 0; c < 4; c++) acc[s][a][b][c] = 0.f;

    FILL(0, 0); CPA_COMMIT();
    FILL(1, 1); CPA_COMMIT();

    int st = 0;
    for (int kt = 0; kt < KT; kt++) {
        CPA_WAIT1();
        __syncthreads();
        {
            int sf = st + 2; if (sf >= 3) sf -= 3;
            if (kt + 2 < KT) FILL(sf, kt + 2);
            CPA_COMMIT();
        }
        const uint32_t stA = sb + (uint32_t)st * STAGE_B;
        const uint32_t stB = stA + 20480u;
#pragma unroll
        for (int ks = 0; ks < 2; ks++) {
            const uint32_t ko = (uint32_t)ks * 32u;
            uint32_t af[4][4];
#pragma unroll
            for (int mf = 0; mf < 4; mf++) {
                uint32_t addr = stA + (uint32_t)(mrow0 + mf * 16) * 80u + ko + lmA;
                LDSM4(af[mf][0], af[mf][1], af[mf][2], af[mf][3], addr);
            }
            uint32_t bf[2][2][4];   // [s][q][...]
#pragma unroll
            for (int s = 0; s < 2; s++)
#pragma unroll
                for (int q = 0; q < 2; q++) {
                    uint32_t addr = stB
                        + (uint32_t)(s * 64 + ncol0 + q * 16) * 80u + ko + lmB;
                    LDSM4(bf[s][q][0], bf[s][q][1], bf[s][q][2], bf[s][q][3], addr);
                }
#pragma unroll
            for (int s = 0; s < 2; s++)
#pragma unroll
                for (int nf = 0; nf < 4; nf++) {
                    uint32_t b0 = bf[s][nf >> 1][(nf & 1) * 2];
                    uint32_t b1 = bf[s][nf >> 1][(nf & 1) * 2 + 1];
#pragma unroll
                    for (int mf = 0; mf < 4; mf++)
                        HMMA(acc[s][mf][nf], af[mf][0], af[mf][1], af[mf][2],
                             af[mf][3], b0, b1);
                }
        }
        if (++st == 3) st = 0;
    }

    // ---- epilogue (accumulators in registers) ----
#pragma unroll
    for (int mf = 0; mf < 4; mf++) {
#pragma unroll
        for (int i = 0; i < 2; i++) {
            const int m = mbase + mrow0 + mf * 16 + grp + i * 8;
            if (m >= cnt) continue;
            const size_t gi = (size_t)off + m;
            if (G1) {
                __half* dp = g_Hf + gi * FF + nb * 64 + ncol0 + 2 * tig;
#pragma unroll
                for (int nf = 0; nf < 4; nf++) {
                    float g0 = acc[0][mf][nf][2 * i];
                    float g1 = acc[0][mf][nf][2 * i + 1];
                    float u0 = acc[1][mf][nf][2 * i];
                    float u1 = acc[1][mf][nf][2 * i + 1];
                    float v0 = g0 / (1.f + expf(-g0)) * u0;
                    float v1 = g1 / (1.f + expf(-g1)) * u1;
                    *(__half2*)(dp + nf * 8) = __floats2half2_rn(v0, v1);
                }
            } else {
                const int   tokn = g_atok[gi];
                const int   slot = g_aslot[gi];
                const float w    = g_aw[gi];
                float* cp = &g_OutK[slot][(size_t)tokn * DD + nb * 128 + ncol0 + 2 * tig];
#pragma unroll
                for (int s = 0; s < 2; s++)
#pragma unroll
                    for (int nf = 0; nf < 4; nf++)
                        *(float2*)(cp + s * 64 + nf * 8) = make_float2(
                            w * acc[s][mf][nf][2 * i], w * acc[s][mf][nf][2 * i + 1]);
            }
        }
    }
#undef FILL
}

__global__ void finalize_kernel(float* __restrict__ out) {
    size_t idx = (size_t)blockIdx.x * blockDim.x + threadIdx.x;
    const size_t total = (size_t)NTOK * DD / 4;
    if (idx >= total) return;
    float4 a = ((const float4*)g_OutK[0])[idx];
    float4 b = ((const float4*)g_OutK[1])[idx];
    float4 r; r.x = a.x + b.x; r.y = a.y + b.y; r.z = a.z + b.z; r.w = a.w + b.w;
    ((float4*)out)[idx] = r;
}

// ---------------- launcher --------------------------------------------------
extern "C" void kernel_launch(void* const* d_in, const int* in_sizes, int n_in,
                              void* d_out, int out_size) {
    const float* x   = (const float*)d_in[0];  // [B,T,D]
    const float* W13 = (const float*)d_in[1];  // [E,D,2F]
    const float* W2  = (const float*)d_in[2];  // [E,F,D]
    const float* Wr  = (const float*)d_in[3];  // [D,E]
    float* out = (float*)d_out;

    // transposes first: W13 variant also zeroes cursors
    {   // W13: [E][1024][5504] -> K-major [E][5504][1024]
        dim3 g(NB13 / 32, DD / 64, EE);
        trans_f16_kernel<DD, NB13, 1><<<g, dim3(32, 8)>>>(W13);
    }
    {   // W2: [E][2752][1024] -> K-major [E][1024][2752]
        dim3 g(DD / 32, FF / 64, EE);
        trans_f16_kernel<FF, DD, 0><<<g, dim3(32, 8)>>>(W2);
    }

    router_kernel<<<NTOK / 8, 256>>>(x, Wr);   // writes g_xf + assignment lists

    cudaFuncSetAttribute(hgemm_tc_kernel<true>,
                         cudaFuncAttributeMaxDynamicSharedMemorySize, SMEM_GEMM);
    cudaFuncSetAttribute(hgemm_tc_kernel<false>,
                         cudaFuncAttributeMaxDynamicSharedMemorySize, SMEM_GEMM);

    dim3 g1(MT256, FF / 64, EE);        // (10, 43, 8) m-fastest
    hgemm_tc_kernel<true><<<g1, 256, SMEM_GEMM>>>();

    dim3 g2(DD / 128, MT256, EE);       // (8, 10, 8) nb-fastest
    hgemm_tc_kernel<false><<<g2, 256, SMEM_GEMM>>>();

    finalize_kernel<<<(NTOK * DD / 4) / 256, 256>>>(out);
}

// round 16
// speedup vs baseline: 1.1095x; 1.1095x over previous
#include <cuda_runtime.h>
#include <cuda_fp16.h>
#include <math.h>
#include <stdint.h>

#define DD   1024
#define FF   2752
#define EE   8
#define NTOK 8192
#define NA   16384
#define NB13 (2*FF)   /* 5504 */
#define MTILES 20     /* m-tile capacity/expert: 2560 rows (E[cnt]=2048, sigma~42 -> 12σ) */
#define ECAP  (MTILES * 128)   /* 2560 */

// ---------------- scratch (static device globals; no allocation) ----------
__device__ int   g_cursor[EE];
__device__ int   g_atok[EE * ECAP];
__device__ int   g_aslot[EE * ECAP];
__device__ float g_aw[EE * ECAP];

__device__ __half g_xf[(size_t)NTOK * DD];            // fp16 x
__device__ __half g_W13f[(size_t)EE * NB13 * DD];     // K-major [E][N][K]
__device__ __half g_W2f[(size_t)EE * DD * FF];        // K-major [E][N][K]
__device__ __half g_Hf[(size_t)EE * ECAP * FF];       // fp16 H (capacity layout)
__device__ float  g_OutK[2][(size_t)NTOK * DD];

// ---------------- helpers ---------------------------------------------------
__device__ __forceinline__ uint32_t smem_u32(const void* p) {
    uint32_t a;
    asm("{ .reg .u64 t; cvta.to.shared.u64 t, %1; cvt.u32.u64 %0, t; }"
        : "=r"(a) : "l"(p));
    return a;
}
#define CPA16(dst, src) \
    asm volatile("cp.async.cg.shared.global [%0], [%1], 16;\n" :: "r"(dst), "l"(src) : "memory")
#define CPA_COMMIT()  asm volatile("cp.async.commit_group;\n" ::: "memory")
#define CPA_WAIT2()   asm volatile("cp.async.wait_group 2;\n" ::: "memory")

#define HMMA(d, a0, a1, a2, a3, b0, b1)                                        \
    asm volatile(                                                              \
        "mma.sync.aligned.m16n8k16.row.col.f32.f16.f16.f32 "                   \
        "{%0,%1,%2,%3}, {%4,%5,%6,%7}, {%8,%9}, {%0,%1,%2,%3};\n"              \
        : "+f"((d)[0]), "+f"((d)[1]), "+f"((d)[2]), "+f"((d)[3])               \
        : "r"(a0), "r"(a1), "r"(a2), "r"(a3), "r"(b0), "r"(b1))

#define LDSM4(r0, r1, r2, r3, addr)                                            \
    asm volatile("ldmatrix.sync.aligned.m8n8.x4.shared.b16 {%0,%1,%2,%3}, [%4];" \
        : "=r"(r0), "=r"(r1), "=r"(r2), "=r"(r3) : "r"(addr))

// ---------------- small kernels -------------------------------------------
// transpose: src fp32 [E][KSRC][NSRC] -> dst fp16 K-major [E][NSRC][KSRC]
// W13SEL variant also zeroes the per-expert cursors (runs first in the chain).
template <int KSRC, int NSRC, int W13SEL>
__global__ void trans_f16_kernel(const float* __restrict__ src) {
    __shared__ float tile[64][33];
    const int e  = blockIdx.z;
    const int n0 = blockIdx.x * 32;
    const int k0 = blockIdx.y * 64;
    const int tx = threadIdx.x, ty = threadIdx.y;  // (32, 8)
    if (W13SEL && blockIdx.x == 0 && blockIdx.y == 0 && blockIdx.z == 0 &&
        ty == 0 && tx < EE) {
        g_cursor[tx] = 0;
    }
    const float* s = src + (size_t)e * KSRC * NSRC;
#pragma unroll
    for (int i = 0; i < 8; i++) {
        int k = ty + i * 8;
        tile[k][tx] = s[(size_t)(k0 + k) * NSRC + n0 + tx];
    }
    __syncthreads();
    __half* d = (W13SEL ? g_W13f : g_W2f) + (size_t)e * NSRC * KSRC;
#pragma unroll
    for (int i = 0; i < 4; i++) {
        int ny = ty + i * 8;
        __half2 p = __floats2half2_rn(tile[2 * tx][ny], tile[2 * tx + 1][ny]);
        *(__half2*)(d + (size_t)(n0 + ny) * KSRC + k0 + 2 * tx) = p;
    }
}

// router + fp16 conversion of x + direct assignment-list build (fused).
__global__ void router_kernel(const float* __restrict__ x,
                              const float* __restrict__ Wr) {
    int warp = (int)((blockIdx.x * blockDim.x + threadIdx.x) >> 5);
    int lane = threadIdx.x & 31;
    if (warp >= NTOK) return;
    const float* xr = x + (size_t)warp * DD;
    float acc[EE];
#pragma unroll
    for (int e = 0; e < EE; e++) acc[e] = 0.f;
    for (int d4 = lane; d4 < DD / 4; d4 += 32) {
        float4 v = ((const float4*)xr)[d4];
        __half2 p0 = __floats2half2_rn(v.x, v.y);
        __half2 p1 = __floats2half2_rn(v.z, v.w);
        *(uint2*)(g_xf + (size_t)warp * DD + d4 * 4) =
            make_uint2(*(uint32_t*)&p0, *(uint32_t*)&p1);
        const float* xv4 = (const float*)&v;
#pragma unroll
        for (int q = 0; q < 4; q++) {
            float xv = xv4[q];
            const float4* wp = (const float4*)(Wr + (size_t)(d4 * 4 + q) * EE);
            float4 w0 = wp[0], w1 = wp[1];
            acc[0] += xv * w0.x; acc[1] += xv * w0.y;
            acc[2] += xv * w0.z; acc[3] += xv * w0.w;
            acc[4] += xv * w1.x; acc[5] += xv * w1.y;
            acc[6] += xv * w1.z; acc[7] += xv * w1.w;
        }
    }
#pragma unroll
    for (int e = 0; e < EE; e++) {
#pragma unroll
        for (int o = 16; o; o >>= 1)
            acc[e] += __shfl_xor_sync(0xffffffffu, acc[e], o);
    }
    if (lane == 0) {
        int i0 = 0;
#pragma unroll
        for (int e = 1; e < EE; e++) if (acc[e] > acc[i0]) i0 = e;
        int i1 = (i0 == 0) ? 1 : 0;
#pragma unroll
        for (int e = 0; e < EE; e++)
            if (e != i0 && acc[e] > acc[i1]) i1 = e;
        float w0 = 1.f / (1.f + expf(acc[i1] - acc[i0]));
        float w1 = 1.f - w0;
        int p0 = atomicAdd(&g_cursor[i0], 1);
        int a0 = i0 * ECAP + p0;
        g_atok[a0] = warp; g_aslot[a0] = 0; g_aw[a0] = w0;
        int p1 = atomicAdd(&g_cursor[i1], 1);
        int a1 = i1 * ECAP + p1;
        g_atok[a1] = warp; g_aslot[a1] = 1; g_aw[a1] = w1;
    }
}

// ---------------- fp16 tensor-core grouped GEMM (R14 core + 4 stages) ------
// CTA: M=128, K-chunk 32, 256 threads, 2 CTAs/SM, 4-stage cp.async
// (wait_group 2 -> two chunks of lookahead beyond the consumed stage).
//   G1: N = 64 gate + 64 up (fused SwiGLU -> fp16 H); grid m-fastest.
//   G2: N = 128 out cols (scaled scatter to OutK); grid nb-fastest.
// Per-expert rows at fixed offset e*ECAP; cnt read from g_cursor.
// 8 warps = 4(m:32) x 2(n:32); each warp: 2 acc sets (G1 gate/up, G2 n/n+64).
// smem/stage: A[128 rows][80B] + B[128 rows][80B] = 20480B; 4 stages (80KB).
// rows = 32 fp16 of K (64B data + 16B pad). ldmatrix.m8n8.x4 fragments.

#define STAGE_B   20480u
#define SMEM_GEMM (4 * 20480)

template <bool G1>
__global__ void __launch_bounds__(256, 2)
hgemm_tc_kernel() {
    constexpr int KDIM = G1 ? DD : FF;
    constexpr int KT   = KDIM / 32;

    const int e     = blockIdx.z;
    const int cnt   = g_cursor[e];
    const int mtile = G1 ? blockIdx.x : blockIdx.y;   // G2: nb-fastest
    const int nb    = G1 ? blockIdx.y : blockIdx.x;
    const int mbase = mtile * 128;
    if (mbase >= cnt) return;
    const int off = e * ECAP;

    extern __shared__ __align__(16) uint32_t smw[];
    const uint32_t sb = smem_u32(smw);

    const int tid  = threadIdx.x;
    const int warp = tid >> 5, lane = tid & 31;
    const int grp  = lane >> 2, tig = lane & 3;
    const int mrow0 = (warp >> 1) * 32;
    const int ncol0 = (warp & 1) * 32;

    // ldmatrix per-lane offsets (bytes within a tile):
    const uint32_t lmA = (uint32_t)(((lane & 7) + ((lane >> 3) & 1) * 8) * 80
                                    + (lane >> 4) * 16);
    const uint32_t lmB = (uint32_t)(((lane & 7) + (lane >> 4) * 8) * 80
                                    + ((lane >> 3) & 1) * 16);

    // ---- fill setup: thread -> (row = tid&127, half = tid>>7); 2 x 16B ----
    const int fr = tid & 127, fh = tid >> 7;
    const __half* aP;
    {
        int rg = mbase + fr; if (rg >= cnt) rg = cnt - 1;
        if (G1) aP = g_xf + (size_t)g_atok[off + rg] * DD + fh * 16;
        else    aP = g_Hf + (size_t)(off + rg) * FF + fh * 16;
    }
    const __half* bP;
    {
        if (G1) {
            int n = (fr < 64) ? (nb * 64 + fr) : (FF + nb * 64 + (fr - 64));
            bP = g_W13f + ((size_t)e * NB13 + n) * DD + fh * 16;
        } else {
            int n = nb * 128 + fr;
            bP = g_W2f + ((size_t)e * DD + n) * FF + fh * 16;
        }
    }
    const uint32_t offA = (uint32_t)fr * 80u + (uint32_t)fh * 32u;
    const uint32_t offB = 10240u + offA;

#define FILL(st, kt) do {                                                      \
    uint32_t _a = sb + (uint32_t)(st) * STAGE_B + offA;                        \
    uint32_t _b = sb + (uint32_t)(st) * STAGE_B + offB;                        \
    const __half* _as = aP + (kt) * 32;                                        \
    const __half* _bs = bP + (kt) * 32;                                        \
    CPA16(_a,      _as);                                                       \
    CPA16(_a + 16, _as + 8);                                                   \
    CPA16(_b,      _bs);                                                       \
    CPA16(_b + 16, _bs + 8);                                                   \
} while (0)

    float acc[2][2][4][4];
#pragma unroll
    for (int s = 0; s < 2; s++)
#pragma unroll
        for (int a = 0; a < 2; a++)
#pragma unroll
            for (int b = 0; b < 4; b++)
#pragma unroll
                for (int c = 0; c < 4; c++) acc[s][a][b][c] = 0.f;

    FILL(0, 0); CPA_COMMIT();
    FILL(1, 1); CPA_COMMIT();
    FILL(2, 2); CPA_COMMIT();

    int st = 0;
    for (int kt = 0; kt < KT; kt++) {
        CPA_WAIT2();
        __syncthreads();
        {
            int sf = st + 3; if (sf >= 4) sf -= 4;
            if (kt + 3 < KT) FILL(sf, kt + 3);
            CPA_COMMIT();
        }
        const uint32_t stA = sb + (uint32_t)st * STAGE_B;
        const uint32_t stB = stA + 10240u;
#pragma unroll
        for (int ks = 0; ks < 2; ks++) {
            const uint32_t ko = (uint32_t)ks * 32u;
            uint32_t af[2][4];
#pragma unroll
            for (int mf = 0; mf < 2; mf++) {
                uint32_t addr = stA + (uint32_t)(mrow0 + mf * 16) * 80u + ko + lmA;
                LDSM4(af[mf][0], af[mf][1], af[mf][2], af[mf][3], addr);
            }
            uint32_t bf[2][2][4];   // [s][q][b0_t0,b1_t0,b0_t1,b1_t1]
#pragma unroll
            for (int s = 0; s < 2; s++)
#pragma unroll
                for (int q = 0; q < 2; q++) {
                    uint32_t addr = stB
                        + (uint32_t)(s * 64 + ncol0 + q * 16) * 80u + ko + lmB;
                    LDSM4(bf[s][q][0], bf[s][q][1], bf[s][q][2], bf[s][q][3], addr);
                }
#pragma unroll
            for (int s = 0; s < 2; s++)
#pragma unroll
                for (int nf = 0; nf < 4; nf++) {
                    uint32_t b0 = bf[s][nf >> 1][(nf & 1) * 2];
                    uint32_t b1 = bf[s][nf >> 1][(nf & 1) * 2 + 1];
                    HMMA(acc[s][0][nf], af[0][0], af[0][1], af[0][2], af[0][3], b0, b1);
                    HMMA(acc[s][1][nf], af[1][0], af[1][1], af[1][2], af[1][3], b0, b1);
                }
        }
        if (++st == 4) st = 0;
    }

    // ---- epilogue (accumulators in registers) ----
#pragma unroll
    for (int mf = 0; mf < 2; mf++) {
#pragma unroll
        for (int i = 0; i < 2; i++) {
            const int m = mbase + mrow0 + mf * 16 + grp + i * 8;
            if (m >= cnt) continue;
            const size_t gi = (size_t)off + m;
            if (G1) {
                __half* dp = g_Hf + gi * FF + nb * 64 + ncol0 + 2 * tig;
#pragma unroll
                for (int nf = 0; nf < 4; nf++) {
                    float g0 = acc[0][mf][nf][2 * i];
                    float g1 = acc[0][mf][nf][2 * i + 1];
                    float u0 = acc[1][mf][nf][2 * i];
                    float u1 = acc[1][mf][nf][2 * i + 1];
                    float v0 = g0 / (1.f + expf(-g0)) * u0;
                    float v1 = g1 / (1.f + expf(-g1)) * u1;
                    *(__half2*)(dp + nf * 8) = __floats2half2_rn(v0, v1);
                }
            } else {
                const int   tokn = g_atok[gi];
                const int   slot = g_aslot[gi];
                const float w    = g_aw[gi];
                float* cp = &g_OutK[slot][(size_t)tokn * DD + nb * 128 + ncol0 + 2 * tig];
#pragma unroll
                for (int s = 0; s < 2; s++)
#pragma unroll
                    for (int nf = 0; nf < 4; nf++)
                        *(float2*)(cp + s * 64 + nf * 8) = make_float2(
                            w * acc[s][mf][nf][2 * i], w * acc[s][mf][nf][2 * i + 1]);
            }
        }
    }
#undef FILL
}

__global__ void finalize_kernel(float* __restrict__ out) {
    size_t idx = (size_t)blockIdx.x * blockDim.x + threadIdx.x;
    const size_t total = (size_t)NTOK * DD / 4;
    if (idx >= total) return;
    float4 a = ((const float4*)g_OutK[0])[idx];
    float4 b = ((const float4*)g_OutK[1])[idx];
    float4 r; r.x = a.x + b.x; r.y = a.y + b.y; r.z = a.z + b.z; r.w = a.w + b.w;
    ((float4*)out)[idx] = r;
}

// ---------------- launcher --------------------------------------------------
extern "C" void kernel_launch(void* const* d_in, const int* in_sizes, int n_in,
                              void* d_out, int out_size) {
    const float* x   = (const float*)d_in[0];  // [B,T,D]
    const float* W13 = (const float*)d_in[1];  // [E,D,2F]
    const float* W2  = (const float*)d_in[2];  // [E,F,D]
    const float* Wr  = (const float*)d_in[3];  // [D,E]
    float* out = (float*)d_out;

    // transposes first: W13 variant also zeroes cursors
    {   // W13: [E][1024][5504] -> K-major [E][5504][1024]
        dim3 g(NB13 / 32, DD / 64, EE);
        trans_f16_kernel<DD, NB13, 1><<<g, dim3(32, 8)>>>(W13);
    }
    {   // W2: [E][2752][1024] -> K-major [E][1024][2752]
        dim3 g(DD / 32, FF / 64, EE);
        trans_f16_kernel<FF, DD, 0><<<g, dim3(32, 8)>>>(W2);
    }

    router_kernel<<<NTOK / 8, 256>>>(x, Wr);   // writes g_xf + assignment lists

    cudaFuncSetAttribute(hgemm_tc_kernel<true>,
                         cudaFuncAttributeMaxDynamicSharedMemorySize, SMEM_GEMM);
    cudaFuncSetAttribute(hgemm_tc_kernel<false>,
                         cudaFuncAttributeMaxDynamicSharedMemorySize, SMEM_GEMM);

    dim3 g1(MTILES, FF / 64, EE);       // (20, 43, 8) m-fastest
    hgemm_tc_kernel<true><<<g1, 256, SMEM_GEMM>>>();

    dim3 g2(DD / 128, MTILES, EE);      // (8, 20, 8) nb-fastest
    hgemm_tc_kernel<false><<<g2, 256, SMEM_GEMM>>>();

    finalize_kernel<<<(NTOK * DD / 4) / 256, 256>>>(out);
}

// round 17
// speedup vs baseline: 1.1144x; 1.0044x over previous
#include <cuda_runtime.h>
#include <cuda_fp16.h>
#include <math.h>
#include <stdint.h>

#define DD   1024
#define FF   2752
#define EE   8
#define NTOK 8192
#define NA   16384
#define NB13 (2*FF)   /* 5504 */
#define MTILES 20     /* m-tile capacity/expert: 2560 rows (E[cnt]=2048, sigma~42 -> 12σ) */
#define ECAP  (MTILES * 128)   /* 2560 */

// ---------------- scratch (static device globals; no allocation) ----------
__device__ int   g_cursor[EE];
__device__ int   g_atok[EE * ECAP];
__device__ int   g_aslot[EE * ECAP];
__device__ float g_aw[EE * ECAP];

__device__ __half g_xf[(size_t)NTOK * DD];            // fp16 x
__device__ __half g_W13f[(size_t)EE * NB13 * DD];     // K-major [E][N][K]
__device__ __half g_W2f[(size_t)EE * DD * FF];        // K-major [E][N][K]
__device__ __half g_Hf[(size_t)EE * ECAP * FF];       // fp16 H (capacity layout)
__device__ float  g_OutK[2][(size_t)NTOK * DD];

// ---------------- helpers ---------------------------------------------------
__device__ __forceinline__ uint32_t smem_u32(const void* p) {
    uint32_t a;
    asm("{ .reg .u64 t; cvta.to.shared.u64 t, %1; cvt.u32.u64 %0, t; }"
        : "=r"(a) : "l"(p));
    return a;
}
#define CPA16(dst, src) \
    asm volatile("cp.async.cg.shared.global [%0], [%1], 16;\n" :: "r"(dst), "l"(src) : "memory")
#define CPA_COMMIT()  asm volatile("cp.async.commit_group;\n" ::: "memory")
#define CPA_WAIT1()   asm volatile("cp.async.wait_group 1;\n" ::: "memory")

#define HMMA(d, a0, a1, a2, a3, b0, b1)                                        \
    asm volatile(                                                              \
        "mma.sync.aligned.m16n8k16.row.col.f32.f16.f16.f32 "                   \
        "{%0,%1,%2,%3}, {%4,%5,%6,%7}, {%8,%9}, {%0,%1,%2,%3};\n"              \
        : "+f"((d)[0]), "+f"((d)[1]), "+f"((d)[2]), "+f"((d)[3])               \
        : "r"(a0), "r"(a1), "r"(a2), "r"(a3), "r"(b0), "r"(b1))

#define LDSM4(r0, r1, r2, r3, addr)                                            \
    asm volatile("ldmatrix.sync.aligned.m8n8.x4.shared.b16 {%0,%1,%2,%3}, [%4];" \
        : "=r"(r0), "=r"(r1), "=r"(r2), "=r"(r3) : "r"(addr))

// ---------------- small kernels -------------------------------------------
// Fused weight transpose+convert for BOTH weights in one launch.
// Linear block id: [0, NW13) -> W13 ([E][1024][5504] -> [E][5504][1024]),
//                  [NW13, NW13+NW2) -> W2 ([E][2752][1024] -> [E][1024][2752]).
// Per-tile geometry identical to the old kernels: 32 n-cols x 64 k-rows,
// block (32, 8). Block 0 also zeroes the per-expert cursors.
#define W13_GX (NB13 / 32)   /* 172 */
#define W13_GY (DD / 64)     /* 16  */
#define NW13   (W13_GX * W13_GY * EE)   /* 22016 */
#define W2_GX  (DD / 32)     /* 32  */
#define W2_GY  (FF / 64)     /* 43  */
#define NW2    (W2_GX * W2_GY * EE)     /* 11008 */

__global__ void trans_both_kernel(const float* __restrict__ W13,
                                  const float* __restrict__ W2) {
    __shared__ float tile[64][33];
    const int tx = threadIdx.x, ty = threadIdx.y;  // (32, 8)
    const int bid = blockIdx.x;
    if (bid == 0 && ty == 0 && tx < EE) g_cursor[tx] = 0;

    int KSRC, NSRC, e, n0, k0;
    const float* s;
    __half* dbase;
    if (bid < NW13) {
        KSRC = DD; NSRC = NB13;
        int r = bid;
        int gx = r % W13_GX; r /= W13_GX;
        int gy = r % W13_GY; e = r / W13_GY;
        n0 = gx * 32; k0 = gy * 64;
        s = W13 + (size_t)e * KSRC * NSRC;
        dbase = g_W13f + (size_t)e * NSRC * KSRC;
    } else {
        KSRC = FF; NSRC = DD;
        int r = bid - NW13;
        int gx = r % W2_GX; r /= W2_GX;
        int gy = r % W2_GY; e = r / W2_GY;
        n0 = gx * 32; k0 = gy * 64;
        s = W2 + (size_t)e * KSRC * NSRC;
        dbase = g_W2f + (size_t)e * NSRC * KSRC;
    }
#pragma unroll
    for (int i = 0; i < 8; i++) {
        int k = ty + i * 8;
        tile[k][tx] = s[(size_t)(k0 + k) * NSRC + n0 + tx];
    }
    __syncthreads();
#pragma unroll
    for (int i = 0; i < 4; i++) {
        int ny = ty + i * 8;
        __half2 p = __floats2half2_rn(tile[2 * tx][ny], tile[2 * tx + 1][ny]);
        *(__half2*)(dbase + (size_t)(n0 + ny) * KSRC + k0 + 2 * tx) = p;
    }
}

// router + fp16 conversion of x + direct assignment-list build (fused).
__global__ void router_kernel(const float* __restrict__ x,
                              const float* __restrict__ Wr) {
    int warp = (int)((blockIdx.x * blockDim.x + threadIdx.x) >> 5);
    int lane = threadIdx.x & 31;
    if (warp >= NTOK) return;
    const float* xr = x + (size_t)warp * DD;
    float acc[EE];
#pragma unroll
    for (int e = 0; e < EE; e++) acc[e] = 0.f;
    for (int d4 = lane; d4 < DD / 4; d4 += 32) {
        float4 v = ((const float4*)xr)[d4];
        __half2 p0 = __floats2half2_rn(v.x, v.y);
        __half2 p1 = __floats2half2_rn(v.z, v.w);
        *(uint2*)(g_xf + (size_t)warp * DD + d4 * 4) =
            make_uint2(*(uint32_t*)&p0, *(uint32_t*)&p1);
        const float* xv4 = (const float*)&v;
#pragma unroll
        for (int q = 0; q < 4; q++) {
            float xv = xv4[q];
            const float4* wp = (const float4*)(Wr + (size_t)(d4 * 4 + q) * EE);
            float4 w0 = wp[0], w1 = wp[1];
            acc[0] += xv * w0.x; acc[1] += xv * w0.y;
            acc[2] += xv * w0.z; acc[3] += xv * w0.w;
            acc[4] += xv * w1.x; acc[5] += xv * w1.y;
            acc[6] += xv * w1.z; acc[7] += xv * w1.w;
        }
    }
#pragma unroll
    for (int e = 0; e < EE; e++) {
#pragma unroll
        for (int o = 16; o; o >>= 1)
            acc[e] += __shfl_xor_sync(0xffffffffu, acc[e], o);
    }
    if (lane == 0) {
        int i0 = 0;
#pragma unroll
        for (int e = 1; e < EE; e++) if (acc[e] > acc[i0]) i0 = e;
        int i1 = (i0 == 0) ? 1 : 0;
#pragma unroll
        for (int e = 0; e < EE; e++)
            if (e != i0 && acc[e] > acc[i1]) i1 = e;
        float w0 = 1.f / (1.f + expf(acc[i1] - acc[i0]));
        float w1 = 1.f - w0;
        int p0 = atomicAdd(&g_cursor[i0], 1);
        int a0 = i0 * ECAP + p0;
        g_atok[a0] = warp; g_aslot[a0] = 0; g_aw[a0] = w0;
        int p1 = atomicAdd(&g_cursor[i1], 1);
        int a1 = i1 * ECAP + p1;
        g_atok[a1] = warp; g_aslot[a1] = 1; g_aw[a1] = w1;
    }
}

// ---------------- fp16 tensor-core grouped GEMM (R14 core, final) ---------
// CTA: M=128, K-chunk 32, 256 threads, 2 CTAs/SM, 3-stage cp.async.
//   G1: N = 64 gate + 64 up (fused SwiGLU -> fp16 H); grid m-fastest.
//   G2: N = 128 out cols (scaled scatter to OutK); grid nb-fastest.
// Per-expert rows at fixed offset e*ECAP; cnt read from g_cursor.
// 8 warps = 4(m:32) x 2(n:32); each warp: 2 acc sets (G1 gate/up, G2 n/n+64).
// smem/stage: A[128 rows][80B] + B[128 rows][80B]; rows = 32 fp16 of K
// (64B data + 16B pad). Fragments via ldmatrix.m8n8.x4 (12/warp/kt).

#define STAGE_B   20480u
#define SMEM_GEMM (3 * 20480)

template <bool G1>
__global__ void __launch_bounds__(256, 2)
hgemm_tc_kernel() {
    constexpr int KDIM = G1 ? DD : FF;
    constexpr int KT   = KDIM / 32;

    const int e     = blockIdx.z;
    const int cnt   = g_cursor[e];
    const int mtile = G1 ? blockIdx.x : blockIdx.y;   // G2: nb-fastest
    const int nb    = G1 ? blockIdx.y : blockIdx.x;
    const int mbase = mtile * 128;
    if (mbase >= cnt) return;
    const int off = e * ECAP;

    extern __shared__ __align__(16) uint32_t smw[];
    const uint32_t sb = smem_u32(smw);

    const int tid  = threadIdx.x;
    const int warp = tid >> 5, lane = tid & 31;
    const int grp  = lane >> 2, tig = lane & 3;
    const int mrow0 = (warp >> 1) * 32;
    const int ncol0 = (warp & 1) * 32;

    // ldmatrix per-lane offsets (bytes within a tile):
    const uint32_t lmA = (uint32_t)(((lane & 7) + ((lane >> 3) & 1) * 8) * 80
                                    + (lane >> 4) * 16);
    const uint32_t lmB = (uint32_t)(((lane & 7) + (lane >> 4) * 8) * 80
                                    + ((lane >> 3) & 1) * 16);

    // ---- fill setup: thread -> (row = tid&127, half = tid>>7); 2 x 16B ----
    const int fr = tid & 127, fh = tid >> 7;
    const __half* aP;
    {
        int rg = mbase + fr; if (rg >= cnt) rg = cnt - 1;
        if (G1) aP = g_xf + (size_t)g_atok[off + rg] * DD + fh * 16;
        else    aP = g_Hf + (size_t)(off + rg) * FF + fh * 16;
    }
    const __half* bP;
    {
        if (G1) {
            int n = (fr < 64) ? (nb * 64 + fr) : (FF + nb * 64 + (fr - 64));
            bP = g_W13f + ((size_t)e * NB13 + n) * DD + fh * 16;
        } else {
            int n = nb * 128 + fr;
            bP = g_W2f + ((size_t)e * DD + n) * FF + fh * 16;
        }
    }
    const uint32_t offA = (uint32_t)fr * 80u + (uint32_t)fh * 32u;
    const uint32_t offB = 10240u + offA;

#define FILL(st, kt) do {                                                      \
    uint32_t _a = sb + (uint32_t)(st) * STAGE_B + offA;                        \
    uint32_t _b = sb + (uint32_t)(st) * STAGE_B + offB;                        \
    const __half* _as = aP + (kt) * 32;                                        \
    const __half* _bs = bP + (kt) * 32;                                        \
    CPA16(_a,      _as);                                                       \
    CPA16(_a + 16, _as + 8);                                                   \
    CPA16(_b,      _bs);                                                       \
    CPA16(_b + 16, _bs + 8);                                                   \
} while (0)

    float acc[2][2][4][4];
#pragma unroll
    for (int s = 0; s < 2; s++)
#pragma unroll
        for (int a = 0; a < 2; a++)
#pragma unroll
            for (int b = 0; b < 4; b++)
#pragma unroll
                for (int c = 0; c < 4; c++) acc[s][a][b][c] = 0.f;

    FILL(0, 0); CPA_COMMIT();
    FILL(1, 1); CPA_COMMIT();

    int st = 0;
    for (int kt = 0; kt < KT; kt++) {
        CPA_WAIT1();
        __syncthreads();
        {
            int sf = st + 2; if (sf >= 3) sf -= 3;
            if (kt + 2 < KT) FILL(sf, kt + 2);
            CPA_COMMIT();
        }
        const uint32_t stA = sb + (uint32_t)st * STAGE_B;
        const uint32_t stB = stA + 10240u;
#pragma unroll
        for (int ks = 0; ks < 2; ks++) {
            const uint32_t ko = (uint32_t)ks * 32u;
            uint32_t af[2][4];
#pragma unroll
            for (int mf = 0; mf < 2; mf++) {
                uint32_t addr = stA + (uint32_t)(mrow0 + mf * 16) * 80u + ko + lmA;
                LDSM4(af[mf][0], af[mf][1], af[mf][2], af[mf][3], addr);
            }
            uint32_t bf[2][2][4];   // [s][q][b0_t0,b1_t0,b0_t1,b1_t1]
#pragma unroll
            for (int s = 0; s < 2; s++)
#pragma unroll
                for (int q = 0; q < 2; q++) {
                    uint32_t addr = stB
                        + (uint32_t)(s * 64 + ncol0 + q * 16) * 80u + ko + lmB;
                    LDSM4(bf[s][q][0], bf[s][q][1], bf[s][q][2], bf[s][q][3], addr);
                }
#pragma unroll
            for (int s = 0; s < 2; s++)
#pragma unroll
                for (int nf = 0; nf < 4; nf++) {
                    uint32_t b0 = bf[s][nf >> 1][(nf & 1) * 2];
                    uint32_t b1 = bf[s][nf >> 1][(nf & 1) * 2 + 1];
                    HMMA(acc[s][0][nf], af[0][0], af[0][1], af[0][2], af[0][3], b0, b1);
                    HMMA(acc[s][1][nf], af[1][0], af[1][1], af[1][2], af[1][3], b0, b1);
                }
        }
        if (++st == 3) st = 0;
    }

    // ---- epilogue (accumulators in registers) ----
#pragma unroll
    for (int mf = 0; mf < 2; mf++) {
#pragma unroll
        for (int i = 0; i < 2; i++) {
            const int m = mbase + mrow0 + mf * 16 + grp + i * 8;
            if (m >= cnt) continue;
            const size_t gi = (size_t)off + m;
            if (G1) {
                __half* dp = g_Hf + gi * FF + nb * 64 + ncol0 + 2 * tig;
#pragma unroll
                for (int nf = 0; nf < 4; nf++) {
                    float g0 = acc[0][mf][nf][2 * i];
                    float g1 = acc[0][mf][nf][2 * i + 1];
                    float u0 = acc[1][mf][nf][2 * i];
                    float u1 = acc[1][mf][nf][2 * i + 1];
                    float v0 = g0 / (1.f + expf(-g0)) * u0;
                    float v1 = g1 / (1.f + expf(-g1)) * u1;
                    *(__half2*)(dp + nf * 8) = __floats2half2_rn(v0, v1);
                }
            } else {
                const int   tokn = g_atok[gi];
                const int   slot = g_aslot[gi];
                const float w    = g_aw[gi];
                float* cp = &g_OutK[slot][(size_t)tokn * DD + nb * 128 + ncol0 + 2 * tig];
#pragma unroll
                for (int s = 0; s < 2; s++)
#pragma unroll
                    for (int nf = 0; nf < 4; nf++)
                        *(float2*)(cp + s * 64 + nf * 8) = make_float2(
                            w * acc[s][mf][nf][2 * i], w * acc[s][mf][nf][2 * i + 1]);
            }
        }
    }
#undef FILL
}

__global__ void finalize_kernel(float* __restrict__ out) {
    size_t idx = (size_t)blockIdx.x * blockDim.x + threadIdx.x;
    const size_t total = (size_t)NTOK * DD / 4;
    if (idx >= total) return;
    float4 a = ((const float4*)g_OutK[0])[idx];
    float4 b = ((const float4*)g_OutK[1])[idx];
    float4 r; r.x = a.x + b.x; r.y = a.y + b.y; r.z = a.z + b.z; r.w = a.w + b.w;
    ((float4*)out)[idx] = r;
}

// ---------------- launcher --------------------------------------------------
extern "C" void kernel_launch(void* const* d_in, const int* in_sizes, int n_in,
                              void* d_out, int out_size) {
    const float* x   = (const float*)d_in[0];  // [B,T,D]
    const float* W13 = (const float*)d_in[1];  // [E,D,2F]
    const float* W2  = (const float*)d_in[2];  // [E,F,D]
    const float* Wr  = (const float*)d_in[3];  // [D,E]
    float* out = (float*)d_out;

    // fused weight transpose+convert (also zeroes cursors)
    trans_both_kernel<<<NW13 + NW2, dim3(32, 8)>>>(W13, W2);

    router_kernel<<<NTOK / 8, 256>>>(x, Wr);   // writes g_xf + assignment lists

    cudaFuncSetAttribute(hgemm_tc_kernel<true>,
                         cudaFuncAttributeMaxDynamicSharedMemorySize, SMEM_GEMM);
    cudaFuncSetAttribute(hgemm_tc_kernel<false>,
                         cudaFuncAttributeMaxDynamicSharedMemorySize, SMEM_GEMM);

    dim3 g1(MTILES, FF / 64, EE);       // (20, 43, 8) m-fastest
    hgemm_tc_kernel<true><<<g1, 256, SMEM_GEMM>>>();

    dim3 g2(DD / 128, MTILES, EE);      // (8, 20, 8) nb-fastest
    hgemm_tc_kernel<false><<<g2, 256, SMEM_GEMM>>>();

    finalize_kernel<<<(NTOK * DD / 4) / 256, 256>>>(out);
}